// round 2
// baseline (speedup 1.0000x reference)
#include <cuda_runtime.h>

// ---------------- problem constants ----------------
#define HW      4096
#define NPIX    (HW*HW)
#define SF      8
#define NPATCH  64
// count semantics derived from reference (f32 thresholds 0.12 / 0.08 on mean of 262144):
#define K1      31458u   // loop1 continues iff count(v>th) <= 31457  <=>  v_(31458) <= th
#define K2      20972u   // loop2 continues iff count(v>th) >= 20972  <=>  v_(20972) >  th
// radix-select window [0.0625, 1.0) over float bit patterns (monotone for v>=0)
#define LOKEY   0x3D800000u
#define HIKEY   0x3F800000u
#define CB_SHIFT 12
#define NCOARSE 8192       // (HIKEY-LOKEY)>>12
#define NSUB    4096       // keys per coarse bin

// ---------------- device scratch (static: no allocation allowed) ----------------
__device__ float        g_blur[NPIX];
__device__ unsigned int g_hist[NPATCH][NCOARSE + 2];   // +under, +over buckets
__device__ unsigned int g_sel [NPATCH][4];              // bin1, above1, bin2, above2
__device__ unsigned int g_key [NPATCH][2];              // exact float-bit keys of A, B
__device__ float        g_th  [NPATCH];

// ---------------- K0: zero histograms ----------------
__global__ void zero_hist() {
    int i = blockIdx.x * blockDim.x + threadIdx.x;
    int total = NPATCH * (NCOARSE + 2);
    if (i < total) ((unsigned int*)g_hist)[i] = 0u;
}

// ---------------- K1: 25-tap box blur + coarse histogram ----------------
// Tap accumulation order: kernel-COLUMN outer, kernel-ROW inner (kh fastest),
// single fmaf chain — matches Eigen SpatialConvolution's contraction order
// (extract_image_patches flattens with kh varying fastest for C=1).
__global__ __launch_bounds__(256) void blur_hist(const float* __restrict__ x,
                                                 const float* __restrict__ bk) {
    __shared__ unsigned int h[NCOARSE + 2];
    for (int i = threadIdx.x; i < NCOARSE + 2; i += 256) h[i] = 0u;
    __syncthreads();

    const float w = bk[0];
    const int col = blockIdx.x * 256 + threadIdx.x;
    const int y0  = blockIdx.y * 128;
    const int patch = (y0 >> 9) * SF + ((blockIdx.x * 256) >> 9);

    float r[5][5];
    #pragma unroll
    for (int i = 0; i < 4; i++) {
        int yy = y0 - 2 + i;
        #pragma unroll
        for (int j = 0; j < 5; j++) {
            int cc = col - 2 + j;
            r[i][j] = (yy >= 0 && yy < HW && cc >= 0 && cc < HW)
                      ? __ldg(&x[yy * HW + cc]) : 0.0f;
        }
    }

    for (int y = y0; y < y0 + 128; y++) {
        int yy = y + 2;
        #pragma unroll
        for (int j = 0; j < 5; j++) {
            int cc = col - 2 + j;
            r[4][j] = (yy < HW && cc >= 0 && cc < HW) ? __ldg(&x[yy * HW + cc]) : 0.0f;
        }
        float acc = 0.0f;
        #pragma unroll
        for (int j = 0; j < 5; j++)       // kw outer
            #pragma unroll
            for (int i = 0; i < 5; i++)   // kh inner (fastest)
                acc = fmaf(r[i][j], w, acc);

        g_blur[y * HW + col] = acc;

        unsigned int key = __float_as_uint(acc);
        unsigned int b;
        if (key < LOKEY)       b = NCOARSE;       // under
        else if (key >= HIKEY) b = NCOARSE + 1;   // over
        else                   b = (key - LOKEY) >> CB_SHIFT;
        atomicAdd(&h[b], 1u);

        #pragma unroll
        for (int i = 0; i < 4; i++)
            #pragma unroll
            for (int j = 0; j < 5; j++)
                r[i][j] = r[i + 1][j];
    }
    __syncthreads();
    unsigned int* gh = g_hist[patch];
    for (int i = threadIdx.x; i < NCOARSE + 2; i += 256)
        if (h[i]) atomicAdd(&gh[i], h[i]);
}

// ---------------- K2: pick coarse bin containing v_(K1) and v_(K2), per patch ----------------
__global__ __launch_bounds__(1024) void coarse_select() {
    __shared__ unsigned int ss[1024];
    const int p = blockIdx.x;
    const int t = threadIdx.x;
    const unsigned int* cnt = g_hist[p];

    unsigned int c[8], s = 0;
    #pragma unroll
    for (int j = 0; j < 8; j++) { c[j] = cnt[t * 8 + j]; s += c[j]; }
    ss[t] = s;
    __syncthreads();
    // Hillis-Steele inclusive suffix scan over 1024 chunk sums
    for (int off = 1; off < 1024; off <<= 1) {
        unsigned int v = (t + off < 1024) ? ss[t + off] : 0u;
        __syncthreads();
        ss[t] += v;
        __syncthreads();
    }
    const unsigned int over = cnt[NCOARSE + 1];
    unsigned int above = ((t < 1023) ? ss[t + 1] : 0u) + over;

    if (t == 0) { g_sel[p][0] = 0u; g_sel[p][1] = K1 - 1u;
                  g_sel[p][2] = 0u; g_sel[p][3] = K2 - 1u; }
    __syncthreads();

    unsigned int a = above;
    #pragma unroll
    for (int j = 7; j >= 0; j--) {
        unsigned int b = (unsigned int)(t * 8 + j);
        unsigned int cb = c[j];
        if (a < K1 && K1 <= a + cb) { g_sel[p][0] = b; g_sel[p][1] = a; }
        if (a < K2 && K2 <= a + cb) { g_sel[p][2] = b; g_sel[p][3] = a; }
        a += cb;
    }
}

// ---------------- K3: refine to the exact float-bit key within the coarse bin ----------------
__global__ __launch_bounds__(1024) void refine() {
    __shared__ unsigned int h1[NSUB], h2[NSUB];
    __shared__ unsigned int ss[1024];
    const int p = blockIdx.x, t = threadIdx.x;
    const unsigned int bin1 = g_sel[p][0], ab1 = g_sel[p][1];
    const unsigned int bin2 = g_sel[p][2], ab2 = g_sel[p][3];

    for (int i = t; i < NSUB; i += 1024) { h1[i] = 0u; h2[i] = 0u; }
    __syncthreads();

    const int pr = p >> 3, pc = p & 7;
    const float* base = g_blur + (pr * 512) * HW + pc * 512;
    for (int i = t; i < 512 * 512; i += 1024) {
        int ly = i >> 9, lx = i & 511;
        unsigned int key = __float_as_uint(base[ly * HW + lx]);
        if (key >= LOKEY && key < HIKEY) {
            unsigned int cb  = (key - LOKEY) >> CB_SHIFT;
            unsigned int sub = key & (NSUB - 1);
            if (cb == bin1) atomicAdd(&h1[sub], 1u);
            if (cb == bin2) atomicAdd(&h2[sub], 1u);
        }
    }
    __syncthreads();

    for (int q = 0; q < 2; q++) {
        unsigned int* hh = q ? h2 : h1;
        const unsigned int r   = q ? (K2 - ab2) : (K1 - ab1);
        const unsigned int bin = q ? bin2 : bin1;

        unsigned int c[4], s = 0;
        #pragma unroll
        for (int j = 0; j < 4; j++) { c[j] = hh[t * 4 + j]; s += c[j]; }
        ss[t] = s;
        __syncthreads();
        for (int off = 1; off < 1024; off <<= 1) {
            unsigned int v = (t + off < 1024) ? ss[t + off] : 0u;
            __syncthreads();
            ss[t] += v;
            __syncthreads();
        }
        unsigned int above = (t < 1023) ? ss[t + 1] : 0u;
        if (t == 0) g_key[p][q] = LOKEY + (bin << CB_SHIFT);   // default (never hit)
        __syncthreads();
        unsigned int a = above;
        #pragma unroll
        for (int j = 3; j >= 0; j--) {
            unsigned int idx = (unsigned int)(t * 4 + j);
            if (a < r && r <= a + c[j])
                g_key[p][q] = LOKEY + (bin << CB_SHIFT) + idx;
            a += c[j];
        }
        __syncthreads();
    }
}

// ---------------- K4: sequential threshold walk (bit-faithful to the reference) ----------------
__global__ void walk() {
    if (blockIdx.x == 0 && threadIdx.x == 0) {
        float th = 0.5f;
        for (int p = 0; p < NPATCH; p++) {
            float A = __uint_as_float(g_key[p][0]);   // v_(31458)
            float B = __uint_as_float(g_key[p][1]);   // v_(20972)
            int g = 0;
            while (A <= th && g < 200000) { th -= 0.0005f; g++; }   // loop1
            g = 0;
            while (B >  th && g < 200000) { th += 0.0005f; g++; }   // loop2
            g_th[p] = th;
        }
    }
}

// ---------------- K5: binarize + morphological close (dilate5 then erode5), fused tile ----------------
#define TS 128
#define HT 136   // tile + halo 4 each side
__global__ __launch_bounds__(256) void close_k(float* __restrict__ out) {
    __shared__ unsigned char a[HT * HT];
    __shared__ unsigned char b[HT * HT];
    __shared__ float sth[NPATCH];
    const int t = threadIdx.x;
    if (t < NPATCH) sth[t] = g_th[t];
    __syncthreads();

    const int gx0 = blockIdx.x * TS - 4;
    const int gy0 = blockIdx.y * TS - 4;

    // binarize (per-pixel patch threshold; out-of-image -> 0, valid for OR/dilate)
    for (int i = t; i < HT * HT; i += 256) {
        int ly = i / HT, lx = i - ly * HT;
        int gy = gy0 + ly, gx = gx0 + lx;
        unsigned char v = 0;
        if (gy >= 0 && gy < HW && gx >= 0 && gx < HW) {
            float bl = g_blur[gy * HW + gx];
            float th = sth[(gy >> 9) * 8 + (gx >> 9)];
            v = (unsigned char)(bl > th);
        }
        a[i] = v;
    }
    __syncthreads();
    // horizontal dilate (OR), cols 2..133
    for (int i = t; i < HT * HT; i += 256) {
        int ly = i / HT, lx = i - ly * HT;
        unsigned char v = 0;
        if (lx >= 2 && lx <= 133)
            v = (unsigned char)(a[i-2] | a[i-1] | a[i] | a[i+1] | a[i+2]);
        b[i] = v;
    }
    __syncthreads();
    // vertical dilate, rows/cols 2..133 -> a
    for (int i = t; i < HT * HT; i += 256) {
        int ly = i / HT, lx = i - ly * HT;
        unsigned char v = 0;
        if (ly >= 2 && ly <= 133 && lx >= 2 && lx <= 133)
            v = (unsigned char)(b[i-2*HT] | b[i-HT] | b[i] | b[i+HT] | b[i+2*HT]);
        a[i] = v;
    }
    __syncthreads();
    // horizontal erode (AND), rows 2..133, cols 4..131; out-of-image cols excluded (=1)
    for (int i = t; i < HT * HT; i += 256) {
        int ly = i / HT, lx = i - ly * HT;
        unsigned char v = 1;
        if (ly >= 2 && ly <= 133 && lx >= 4 && lx <= 131) {
            #pragma unroll
            for (int d = -2; d <= 2; d++) {
                int gx = gx0 + lx + d;
                unsigned char u = (gx >= 0 && gx < HW) ? a[i + d] : (unsigned char)1;
                v = (unsigned char)(v & u);
            }
        }
        b[i] = v;
    }
    __syncthreads();
    // vertical erode + store
    for (int i = t; i < TS * TS; i += 256) {
        int ly = i >> 7, lx = i & 127;
        int sy = ly + 4, sx = lx + 4;
        unsigned char v = 1;
        #pragma unroll
        for (int d = -2; d <= 2; d++) {
            int gy = gy0 + sy + d;
            unsigned char u = (gy >= 0 && gy < HW) ? b[(sy + d) * HT + sx] : (unsigned char)1;
            v = (unsigned char)(v & u);
        }
        out[(gy0 + sy) * HW + (gx0 + sx)] = (float)v;
    }
}

// ---------------- launch ----------------
extern "C" void kernel_launch(void* const* d_in, const int* in_sizes, int n_in,
                              void* d_out, int out_size) {
    const float* x  = (const float*)d_in[0];
    const float* bk = (const float*)d_in[1];
    float* out = (float*)d_out;
    (void)in_sizes; (void)n_in; (void)out_size;

    zero_hist<<<(NPATCH * (NCOARSE + 2) + 255) / 256, 256>>>();
    blur_hist<<<dim3(HW / 256, HW / 128), 256>>>(x, bk);
    coarse_select<<<NPATCH, 1024>>>();
    refine<<<NPATCH, 1024>>>();
    walk<<<1, 32>>>();
    close_k<<<dim3(HW / TS, HW / TS), 256>>>(out);
}